// round 2
// baseline (speedup 1.0000x reference)
#include <cuda_runtime.h>

// Problem constants: B=2, S=2048, E=1024, H=16, D=64
#define NH    16
#define HD    64
#define SEQ   2048
#define BATCH 2
#define EMB   1024
#define MROWS (BATCH*SEQ)   // 4096

// Scratch (device globals — no allocation allowed in kernel_launch)
__device__ float g_Q[BATCH*NH*SEQ*HD];     // [b,h,s,d]
__device__ float g_K[BATCH*NH*SEQ*HD];
__device__ float g_V[BATCH*NH*SEQ*HD];
__device__ float g_CTX[MROWS*EMB];         // [b,s,h*d]
__device__ float g_cos[SEQ*32];
__device__ float g_sin[SEQ*32];

// ---------------------------------------------------------------------------
// RoPE table: cos/sin(pos * invf[i]), invf[i] = 10000^(-i/32), i in [0,32)
// ---------------------------------------------------------------------------
__global__ void rope_table_kernel() {
    int idx = blockIdx.x * blockDim.x + threadIdx.x;
    if (idx >= SEQ * 32) return;
    int pos = idx >> 5;
    int fi  = idx & 31;
    // log2(10000)/32 = 0.415241011860920...
    float invf = exp2f(-(float)fi * 0.41524101186092030f);
    float ang  = (float)pos * invf;
    float s, c;
    sincosf(ang, &s, &c);
    g_cos[idx] = c;
    g_sin[idx] = s;
}

// ---------------------------------------------------------------------------
// NT SGEMM: C[m,n] = sum_k A[m,k] * Bw[n,k] + bias[n]
//   mode 0: plain store to extout [MROWS, EMB]
//   mode 1: store transposed to [b,h,s,d] (V)
//   mode 2: RoPE + store transposed (Q, K)
//   outsel: 0 -> g_Q, 1 -> g_K, 2 -> g_V, 3 -> extout
//   A == nullptr -> use g_CTX
// ---------------------------------------------------------------------------
#define BM 128
#define BN 128
#define BKK 8

__global__ __launch_bounds__(256) void gemm_nt_kernel(
    const float* __restrict__ A, const float* __restrict__ Bw,
    const float* __restrict__ bias, float* __restrict__ extout,
    int mode, int outsel)
{
    __shared__ float As[BKK][BM];
    __shared__ float Bs[BKK][BN];
    const int K = EMB;

    int tid = threadIdx.x;
    int bn = blockIdx.x, bm = blockIdx.y;
    int tr = tid >> 4;      // 0..15 (row group)
    int tc = tid & 15;      // 0..15 (col group)

    const float* Ap = A ? A : (const float*)g_CTX;
    float* outp = (outsel == 0) ? g_Q : (outsel == 1) ? g_K :
                  (outsel == 2) ? g_V : extout;

    const float* Ab = Ap + (size_t)(bm * BM) * K;
    const float* Bb = Bw + (size_t)(bn * BN) * K;

    int lr = tid >> 1;          // 0..127: tile row being loaded
    int lc = (tid & 1) * 4;     // 0 or 4: k offset (float4)

    float acc[8][8];
    #pragma unroll
    for (int i = 0; i < 8; i++)
        #pragma unroll
        for (int j = 0; j < 8; j++) acc[i][j] = 0.f;

    for (int k0 = 0; k0 < K; k0 += BKK) {
        float4 a4 = *(const float4*)(Ab + (size_t)lr * K + k0 + lc);
        float4 b4 = *(const float4*)(Bb + (size_t)lr * K + k0 + lc);
        __syncthreads();   // previous iteration's smem reads done
        As[lc + 0][lr] = a4.x; As[lc + 1][lr] = a4.y;
        As[lc + 2][lr] = a4.z; As[lc + 3][lr] = a4.w;
        Bs[lc + 0][lr] = b4.x; Bs[lc + 1][lr] = b4.y;
        Bs[lc + 2][lr] = b4.z; Bs[lc + 3][lr] = b4.w;
        __syncthreads();
        #pragma unroll
        for (int kk = 0; kk < BKK; kk++) {
            float4 a0 = *(const float4*)&As[kk][tr * 8];
            float4 a1 = *(const float4*)&As[kk][tr * 8 + 4];
            float4 b0 = *(const float4*)&Bs[kk][tc * 8];
            float4 b1 = *(const float4*)&Bs[kk][tc * 8 + 4];
            float ar[8] = {a0.x, a0.y, a0.z, a0.w, a1.x, a1.y, a1.z, a1.w};
            float br[8] = {b0.x, b0.y, b0.z, b0.w, b1.x, b1.y, b1.z, b1.w};
            #pragma unroll
            for (int i = 0; i < 8; i++)
                #pragma unroll
                for (int j = 0; j < 8; j++)
                    acc[i][j] += ar[i] * br[j];
        }
    }

    // Epilogue: bias (+ RoPE) (+ transpose)
    #pragma unroll
    for (int i = 0; i < 8; i++) {
        int mrow = bm * BM + tr * 8 + i;
        int pos  = mrow & (SEQ - 1);
        #pragma unroll
        for (int jj = 0; jj < 4; jj++) {
            int n0 = bn * BN + tc * 8 + jj * 2;
            float v0 = acc[i][jj * 2]     + bias[n0];
            float v1 = acc[i][jj * 2 + 1] + bias[n0 + 1];
            if (mode == 0) {
                outp[(size_t)mrow * EMB + n0]     = v0;
                outp[(size_t)mrow * EMB + n0 + 1] = v1;
            } else {
                if (mode == 2) {
                    int i0 = n0 & 31;   // even; i0+1 <= 31
                    float c0 = g_cos[pos * 32 + i0];
                    float s0 = g_sin[pos * 32 + i0];
                    float c1 = g_cos[pos * 32 + i0 + 1];
                    float s1 = g_sin[pos * 32 + i0 + 1];
                    float r0 = v0 * c0 - v1 * s0;   // x*cos - x_odd*sin
                    float r1 = v1 * c1 + v0 * s1;   // x*cos + x_even*sin
                    v0 = r0; v1 = r1;
                }
                int b = mrow >> 11, srow = mrow & (SEQ - 1);
                int h = n0 >> 6,   d    = n0 & (HD - 1);
                float* dst = outp + ((size_t)((b * NH + h) * SEQ + srow)) * HD + d;
                dst[0] = v0;
                dst[1] = v1;
            }
        }
    }
}

// ---------------------------------------------------------------------------
// Flash-style attention: 1 thread = 1 query row, online softmax.
// grid: (SEQ/128, BATCH*NH), block: 128 threads
// ---------------------------------------------------------------------------
#define TKV 32

__global__ __launch_bounds__(128) void attn_kernel() {
    __shared__ float Ks[TKV][HD];
    __shared__ float Vs[TKV][HD];

    int bh    = blockIdx.y;
    int tid   = threadIdx.x;
    int q_idx = blockIdx.x * 128 + tid;

    const float* Qb = g_Q + (size_t)bh * SEQ * HD;
    const float* Kb = g_K + (size_t)bh * SEQ * HD;
    const float* Vb = g_V + (size_t)bh * SEQ * HD;

    float4 q[16];
    const float4* qp = (const float4*)(Qb + (size_t)q_idx * HD);
    #pragma unroll
    for (int i = 0; i < 16; i++) q[i] = qp[i];

    float4 o[16];
    #pragma unroll
    for (int i = 0; i < 16; i++) o[i] = make_float4(0.f, 0.f, 0.f, 0.f);
    float m = -1e30f, l = 0.f;

    for (int kt = 0; kt < SEQ; kt += TKV) {
        __syncthreads();
        const float4* Kg  = (const float4*)(Kb + (size_t)kt * HD);
        const float4* Vg  = (const float4*)(Vb + (size_t)kt * HD);
        float4* Kss = (float4*)&Ks[0][0];
        float4* Vss = (float4*)&Vs[0][0];
        #pragma unroll
        for (int i = 0; i < 4; i++) {
            Kss[tid + i * 128] = Kg[tid + i * 128];
            Vss[tid + i * 128] = Vg[tid + i * 128];
        }
        __syncthreads();
        #pragma unroll 1
        for (int j = 0; j < TKV; j++) {
            const float4* kv = (const float4*)&Ks[j][0];
            float d0 = 0.f, d1 = 0.f, d2 = 0.f, d3 = 0.f;
            #pragma unroll
            for (int i = 0; i < 16; i++) {
                float4 kk = kv[i];
                d0 += q[i].x * kk.x;
                d1 += q[i].y * kk.y;
                d2 += q[i].z * kk.z;
                d3 += q[i].w * kk.w;
            }
            float s = (d0 + d1 + d2 + d3) * 0.125f;   // / sqrt(64)
            if (s > m) {                               // lazy rescale
                float c = __expf(m - s);
                l *= c;
                #pragma unroll
                for (int i = 0; i < 16; i++) {
                    o[i].x *= c; o[i].y *= c; o[i].z *= c; o[i].w *= c;
                }
                m = s;
            }
            float p = __expf(s - m);
            l += p;
            const float4* vv = (const float4*)&Vs[j][0];
            #pragma unroll
            for (int i = 0; i < 16; i++) {
                float4 v4 = vv[i];
                o[i].x += p * v4.x; o[i].y += p * v4.y;
                o[i].z += p * v4.z; o[i].w += p * v4.w;
            }
        }
    }

    float invl = 1.f / l;
    int b = bh >> 4, h = bh & (NH - 1);
    float* op = g_CTX + ((size_t)(b * SEQ + q_idx) * EMB + h * HD);
    #pragma unroll
    for (int i = 0; i < 16; i++) {
        float4 r = o[i];
        r.x *= invl; r.y *= invl; r.z *= invl; r.w *= invl;
        ((float4*)op)[i] = r;
    }
}

// ---------------------------------------------------------------------------
extern "C" void kernel_launch(void* const* d_in, const int* in_sizes, int n_in,
                              void* d_out, int out_size) {
    const float* x  = (const float*)d_in[0];
    const float* Wq = (const float*)d_in[1];
    const float* bq = (const float*)d_in[2];
    const float* Wk = (const float*)d_in[3];
    const float* bk = (const float*)d_in[4];
    const float* Wv = (const float*)d_in[5];
    const float* bv = (const float*)d_in[6];
    const float* Wo = (const float*)d_in[7];
    const float* bo = (const float*)d_in[8];
    float* out = (float*)d_out;

    rope_table_kernel<<<(SEQ * 32) / 256, 256>>>();

    dim3 ggrid(EMB / BN, MROWS / BM);   // (8, 32)
    gemm_nt_kernel<<<ggrid, 256>>>(x, Wq, bq, nullptr, 2, 0);  // Q (+rope)
    gemm_nt_kernel<<<ggrid, 256>>>(x, Wk, bk, nullptr, 2, 1);  // K (+rope)
    gemm_nt_kernel<<<ggrid, 256>>>(x, Wv, bv, nullptr, 1, 2);  // V

    attn_kernel<<<dim3(SEQ / 128, BATCH * NH), 128>>>();

    gemm_nt_kernel<<<ggrid, 256>>>(nullptr, Wo, bo, out, 0, 3); // out proj
}

// round 15
// speedup vs baseline: 3.5109x; 3.5109x over previous
#include <cuda_runtime.h>
#include <cstdint>

// Problem constants: B=2, S=2048, E=1024, H=16, D=64
#define NH    16
#define HD    64
#define SEQ   2048
#define BATCH 2
#define EMB   1024
#define MROWS (BATCH*SEQ)   // 4096

// Scratch (device globals — no allocation allowed)
__device__ __align__(16) float g_Q[BATCH*NH*SEQ*HD];
__device__ __align__(16) float g_K[BATCH*NH*SEQ*HD];
__device__ __align__(16) float g_V[BATCH*NH*SEQ*HD];
__device__ __align__(16) float g_CTX[MROWS*EMB];
__device__ __align__(16) float g_Xr[MROWS*EMB];      // tf32-rounded x
__device__ __align__(16) float g_W4[4*EMB*EMB];      // tf32-rounded Wq,Wk,Wv,Wo
__device__ float g_cos[SEQ*32];
__device__ float g_sin[SEQ*32];

// ===========================================================================
// Helpers (all baseline PTX, sm_80+ — NO arch-'a' features)
// ===========================================================================
__device__ __forceinline__ uint32_t smem_u32(const void* p) {
    uint32_t a;
    asm("{ .reg .u64 t; cvta.to.shared.u64 t, %1; cvt.u32.u64 %0, t; }"
        : "=r"(a) : "l"(p));
    return a;
}

__device__ __forceinline__ float tf32r(float x) {
    uint32_t u;
    asm("cvt.rna.tf32.f32 %0, %1;" : "=r"(u) : "f"(x));
    return __uint_as_float(u);
}

__device__ __forceinline__ void cp_async16(void* s, const void* g) {
    uint32_t sa = smem_u32(s);
    asm volatile("cp.async.cg.shared.global [%0], [%1], 16;" :: "r"(sa), "l"(g));
}
#define CP_COMMIT asm volatile("cp.async.commit_group;" ::: "memory")
#define CP_WAIT0  asm volatile("cp.async.wait_group 0;" ::: "memory")
#define CP_WAIT1  asm volatile("cp.async.wait_group 1;" ::: "memory")

// m16n8k8 tf32 MMA, fp32 accumulate
__device__ __forceinline__ void mma8(float* c, const uint32_t* a,
                                     uint32_t b0, uint32_t b1) {
    asm volatile(
        "mma.sync.aligned.m16n8k8.row.col.f32.tf32.tf32.f32 "
        "{%0,%1,%2,%3}, {%4,%5,%6,%7}, {%8,%9}, {%0,%1,%2,%3};"
        : "+f"(c[0]), "+f"(c[1]), "+f"(c[2]), "+f"(c[3])
        : "r"(a[0]), "r"(a[1]), "r"(a[2]), "r"(a[3]), "r"(b0), "r"(b1));
}

// ===========================================================================
// RoPE table
// ===========================================================================
__global__ void rope_table_kernel() {
    int idx = blockIdx.x * blockDim.x + threadIdx.x;
    if (idx >= SEQ * 32) return;
    int pos = idx >> 5;
    int fi  = idx & 31;
    float invf = exp2f(-(float)fi * 0.41524101186092030f);  // log2(10000)/32
    float ang  = (float)pos * invf;
    float s, c;
    sincosf(ang, &s, &c);
    g_cos[idx] = c;
    g_sin[idx] = s;
}

// ===========================================================================
// Pre-round x and all 4 weight matrices to tf32 (round-to-nearest)
// Total: 4M + 4M floats = 2M float4
// ===========================================================================
__global__ void round_kernel(const float* __restrict__ x,
                             const float* __restrict__ Wq,
                             const float* __restrict__ Wk,
                             const float* __restrict__ Wv,
                             const float* __restrict__ Wo) {
    int i = blockIdx.x * 256 + threadIdx.x;
    const int XQ = MROWS * EMB / 4;     // 1M float4
    const int WQ = EMB * EMB / 4;       // 256K float4
    const float4* src;
    float4* dst;
    int off;
    if (i < XQ) {
        src = (const float4*)x; dst = (float4*)g_Xr; off = i;
    } else {
        int j = i - XQ;
        int w = j / WQ, r = j % WQ;
        src = (const float4*)((w == 0) ? Wq : (w == 1) ? Wk : (w == 2) ? Wv : Wo);
        dst = (float4*)(g_W4 + (size_t)w * EMB * EMB);
        off = r;
    }
    float4 v = src[off];
    v.x = tf32r(v.x); v.y = tf32r(v.y); v.z = tf32r(v.z); v.w = tf32r(v.w);
    dst[off] = v;
}

// ===========================================================================
// tf32 mma.sync NT GEMM: C[m,n] = sum_k A[m,k]*W[n,k] + bias[n]
// A, W pre-rounded to tf32. Block tile 128x128xK16, 256 thr (8 warps m64xn32).
//   mode 0: plain -> extout;  mode 1: transpose [b,h,s,d]+tf32-round (V)
//   mode 2: RoPE + transpose + round (Q,K)
//   asel: 0 = g_Xr, 1 = g_CTX;  wsel: 0..3 into g_W4
//   outsel: 0 g_Q, 1 g_K, 2 g_V, 3 extout
// ===========================================================================
#define GPAD 20
#define GSTG 3
#define GEMM_SMEM (GSTG * (128*GPAD + 128*GPAD) * 4)   // 61440 B

__global__ __launch_bounds__(256) void gemm_tc(
    const float* __restrict__ bias, float* __restrict__ extout,
    int mode, int outsel, int asel, int wsel)
{
    extern __shared__ float sm[];
    float* As = sm;                       // [GSTG][128][GPAD]
    float* Bs = sm + GSTG * 128 * GPAD;   // [GSTG][128][GPAD]

    const int tid = threadIdx.x;
    const int wid = tid >> 5, lane = tid & 31;
    const int warp_m = (wid & 1) * 64;    // 2 warps along m
    const int warp_n = (wid >> 1) * 32;   // 4 warps along n
    const int bm = blockIdx.y, bn = blockIdx.x;

    const float* A = (asel == 0) ? g_Xr : g_CTX;
    const float* W = g_W4 + (size_t)wsel * EMB * EMB;
    const float* Ab = A + (size_t)bm * 128 * EMB;
    const float* Wb = W + (size_t)bn * 128 * EMB;

    // stage loader: 128 rows x 16 k per matrix = 512 float4, 2 per thread each
    const int lrow = tid >> 2;           // 0..63? no: v = tid + 256*i
    float c[4][4][4];
    #pragma unroll
    for (int a = 0; a < 4; a++)
        #pragma unroll
        for (int b = 0; b < 4; b++)
            #pragma unroll
            for (int r = 0; r < 4; r++) c[a][b][r] = 0.f;

    auto load_stage = [&](int kt, int stg) {
        float* sa = As + stg * 128 * GPAD;
        float* sb = Bs + stg * 128 * GPAD;
        const float* ga = Ab + kt * 16;
        const float* gb = Wb + kt * 16;
        #pragma unroll
        for (int i = 0; i < 2; i++) {
            int v = tid + 256 * i;
            int row = v >> 2, c4 = (v & 3) * 4;
            cp_async16(&sa[row * GPAD + c4], ga + (size_t)row * EMB + c4);
        }
        #pragma unroll
        for (int i = 0; i < 2; i++) {
            int v = tid + 256 * i;
            int row = v >> 2, c4 = (v & 3) * 4;
            cp_async16(&sb[row * GPAD + c4], gb + (size_t)row * EMB + c4);
        }
    };

    load_stage(0, 0); CP_COMMIT;
    load_stage(1, 1); CP_COMMIT;

    const int NKT = EMB / 16;   // 64
    for (int kt = 0; kt < NKT; kt++) {
        int stg = kt % GSTG;
        if (kt + 2 < NKT) { CP_WAIT1; } else { CP_WAIT0; }
        __syncthreads();
        if (kt + 2 < NKT) { load_stage(kt + 2, (kt + 2) % GSTG); CP_COMMIT; }

        const float* sa = As + stg * 128 * GPAD;
        const float* sb = Bs + stg * 128 * GPAD;
        #pragma unroll
        for (int ks = 0; ks < 2; ks++) {
            uint32_t af[4][4];
            #pragma unroll
            for (int mi = 0; mi < 4; mi++) {
                int r = warp_m + mi * 16 + (lane >> 2);
                int k = ks * 8 + (lane & 3);
                af[mi][0] = __float_as_uint(sa[r * GPAD + k]);
                af[mi][1] = __float_as_uint(sa[(r + 8) * GPAD + k]);
                af[mi][2] = __float_as_uint(sa[r * GPAD + k + 4]);
                af[mi][3] = __float_as_uint(sa[(r + 8) * GPAD + k + 4]);
            }
            uint32_t bf[4][2];
            #pragma unroll
            for (int ni = 0; ni < 4; ni++) {
                int n = warp_n + ni * 8 + (lane >> 2);
                int k = ks * 8 + (lane & 3);
                bf[ni][0] = __float_as_uint(sb[n * GPAD + k]);
                bf[ni][1] = __float_as_uint(sb[n * GPAD + k + 4]);
            }
            #pragma unroll
            for (int mi = 0; mi < 4; mi++)
                #pragma unroll
                for (int ni = 0; ni < 4; ni++)
                    mma8(c[mi][ni], af[mi], bf[ni][0], bf[ni][1]);
        }
    }

    // Epilogue
    float* outp = (outsel == 0) ? g_Q : (outsel == 1) ? g_K :
                  (outsel == 2) ? g_V : extout;

    #pragma unroll
    for (int ni = 0; ni < 4; ni++) {
        int n0 = bn * 128 + warp_n + ni * 8 + (lane & 3) * 2;
        float2 bv = *(const float2*)(bias + n0);
        #pragma unroll
        for (int mi = 0; mi < 4; mi++) {
            int r0 = bm * 128 + warp_m + mi * 16 + (lane >> 2);
            #pragma unroll
            for (int half = 0; half < 2; half++) {
                int mrow = r0 + half * 8;
                float v0 = c[mi][ni][half * 2]     + bv.x;
                float v1 = c[mi][ni][half * 2 + 1] + bv.y;
                if (mode == 0) {
                    *(float2*)(extout + (size_t)mrow * EMB + n0) = make_float2(v0, v1);
                } else {
                    int pos = mrow & (SEQ - 1), b = mrow >> 11;
                    if (mode == 2) {
                        int i0 = n0 & 31;
                        float c0 = g_cos[pos * 32 + i0];
                        float s0 = g_sin[pos * 32 + i0];
                        float c1 = g_cos[pos * 32 + i0 + 1];
                        float s1 = g_sin[pos * 32 + i0 + 1];
                        float r0v = v0 * c0 - v1 * s0;
                        float r1v = v1 * c1 + v0 * s1;
                        v0 = r0v; v1 = r1v;
                    }
                    v0 = tf32r(v0); v1 = tf32r(v1);   // feed attention mma exactly
                    int h = n0 >> 6, d = n0 & (HD - 1);
                    *(float2*)(outp + ((size_t)((b * NH + h) * SEQ + pos)) * HD + d) =
                        make_float2(v0, v1);
                }
            }
        }
    }
}

// ===========================================================================
// tf32 mma.sync flash attention. Block: 128 thr (4 warps), 64 queries,
// KV tiles of 64, double-buffered cp.async. Per warp: 16 q rows.
// S = Q K^T via mma; online softmax on fragments; P -> per-warp smem -> PV mma.
// grid: (SEQ/64, BATCH*NH)
// ===========================================================================
#define APAD 68
#define ATT_SMEM ((2*64*APAD /*K*/ + 2*64*APAD /*V*/ + 4*16*APAD /*P*/) * 4)  // 87040

__global__ __launch_bounds__(128) void attn_tc_kernel() {
    extern __shared__ float sm[];
    float* Ks = sm;                    // [2][64][APAD]
    float* Vs = sm + 2 * 64 * APAD;    // [2][64][APAD]
    float* Ps = sm + 4 * 64 * APAD;    // [4][16][APAD]

    const int tid = threadIdx.x, wid = tid >> 5, lane = tid & 31;
    const int bh = blockIdx.y;
    const int q0 = blockIdx.x * 64;

    const float* Qb = g_Q + (size_t)bh * SEQ * HD;
    const float* Kb = g_K + (size_t)bh * SEQ * HD;
    const float* Vb = g_V + (size_t)bh * SEQ * HD;

    // Q fragments, scaled by 1/8 (exact power of 2, stays tf32-exact)
    uint32_t qa[8][4];
    const int qr0 = q0 + wid * 16 + (lane >> 2);
    #pragma unroll
    for (int kk = 0; kk < 8; kk++) {
        int d0 = kk * 8 + (lane & 3);
        qa[kk][0] = __float_as_uint(0.125f * Qb[(size_t)qr0 * HD + d0]);
        qa[kk][1] = __float_as_uint(0.125f * Qb[(size_t)(qr0 + 8) * HD + d0]);
        qa[kk][2] = __float_as_uint(0.125f * Qb[(size_t)qr0 * HD + d0 + 4]);
        qa[kk][3] = __float_as_uint(0.125f * Qb[(size_t)(qr0 + 8) * HD + d0 + 4]);
    }

    float oc[8][4];
    #pragma unroll
    for (int i = 0; i < 8; i++)
        #pragma unroll
        for (int r = 0; r < 4; r++) oc[i][r] = 0.f;
    float m0 = -1e30f, m1 = -1e30f, l0 = 0.f, l1 = 0.f;

    auto load_kv = [&](int kt, int stg) {
        const float* kg = Kb + (size_t)(kt * 64) * HD;
        const float* vg = Vb + (size_t)(kt * 64) * HD;
        float* ks = Ks + stg * 64 * APAD;
        float* vs = Vs + stg * 64 * APAD;
        #pragma unroll
        for (int i = 0; i < 8; i++) {
            int v = tid + 128 * i;       // 1024 float4 per matrix
            int row = v >> 4, c4 = (v & 15) * 4;
            cp_async16(&ks[row * APAD + c4], kg + row * HD + c4);
            cp_async16(&vs[row * APAD + c4], vg + row * HD + c4);
        }
    };

    load_kv(0, 0); CP_COMMIT;
    const int NT = SEQ / 64;   // 32
    float* pw = Ps + wid * 16 * APAD;

    for (int kt = 0; kt < NT; kt++) {
        int stg = kt & 1;
        CP_WAIT0;
        __syncthreads();
        if (kt + 1 < NT) { load_kv(kt + 1, stg ^ 1); CP_COMMIT; }

        const float* ks = Ks + stg * 64 * APAD;
        const float* vs = Vs + stg * 64 * APAD;

        // ---- S = Q K^T (scaled) ----
        float s[8][4];
        #pragma unroll
        for (int i = 0; i < 8; i++)
            #pragma unroll
            for (int r = 0; r < 4; r++) s[i][r] = 0.f;
        #pragma unroll
        for (int kk = 0; kk < 8; kk++) {
            #pragma unroll
            for (int ni = 0; ni < 8; ni++) {
                int key = ni * 8 + (lane >> 2);
                int d   = kk * 8 + (lane & 3);
                uint32_t b0 = __float_as_uint(ks[key * APAD + d]);
                uint32_t b1 = __float_as_uint(ks[key * APAD + d + 4]);
                mma8(s[ni], qa[kk], b0, b1);
            }
        }

        // ---- online softmax on fragments ----
        float mx0 = -1e30f, mx1 = -1e30f;
        #pragma unroll
        for (int ni = 0; ni < 8; ni++) {
            mx0 = fmaxf(mx0, fmaxf(s[ni][0], s[ni][1]));
            mx1 = fmaxf(mx1, fmaxf(s[ni][2], s[ni][3]));
        }
        mx0 = fmaxf(mx0, __shfl_xor_sync(0xffffffffu, mx0, 1));
        mx0 = fmaxf(mx0, __shfl_xor_sync(0xffffffffu, mx0, 2));
        mx1 = fmaxf(mx1, __shfl_xor_sync(0xffffffffu, mx1, 1));
        mx1 = fmaxf(mx1, __shfl_xor_sync(0xffffffffu, mx1, 2));
        float nm0 = fmaxf(m0, mx0), nm1 = fmaxf(m1, mx1);
        float a0 = __expf(m0 - nm0), a1 = __expf(m1 - nm1);
        l0 *= a0; l1 *= a1;
        #pragma unroll
        for (int ni = 0; ni < 8; ni++) {
            oc[ni][0] *= a0; oc[ni][1] *= a0;
            oc[ni][2] *= a1; oc[ni][3] *= a1;
        }
        m0 = nm0; m1 = nm1;

        #pragma unroll
        for (int ni = 0; ni < 8; ni++) {
            float p00 = __expf(s[ni][0] - m0);
            float p01 = __expf(s[ni][1] - m0);
            float p10 = __expf(s[ni][2] - m1);
            float p11 = __expf(s[ni][3] - m1);
            l0 += p00 + p01;
            l1 += p10 + p11;
            int col = ni * 8 + (lane & 3) * 2;
            *(float2*)&pw[(lane >> 2) * APAD + col] =
                make_float2(tf32r(p00), tf32r(p01));
            *(float2*)&pw[((lane >> 2) + 8) * APAD + col] =
                make_float2(tf32r(p10), tf32r(p11));
        }
        __syncwarp();

        // ---- O += P V ----
        #pragma unroll
        for (int kk = 0; kk < 8; kk++) {
            uint32_t pa[4];
            int kcol = kk * 8 + (lane & 3);
            pa[0] = __float_as_uint(pw[(lane >> 2) * APAD + kcol]);
            pa[1] = __float_as_uint(pw[((lane >> 2) + 8) * APAD + kcol]);
            pa[2] = __float_as_uint(pw[(lane >> 2) * APAD + kcol + 4]);
            pa[3] = __float_as_uint(pw[((lane >> 2) + 8) * APAD + kcol + 4]);
            #pragma unroll
            for (int ni = 0; ni < 8; ni++) {
                int key = kk * 8 + (lane & 3);
                int d   = ni * 8 + (lane >> 2);
                uint32_t b0 = __float_as_uint(vs[key * APAD + d]);
                uint32_t b1 = __float_as_uint(vs[(key + 4) * APAD + d]);
                mma8(oc[ni], pa, b0, b1);
            }
        }
        __syncwarp();
    }

    // finalize: row sums across quad, normalize, store to g_CTX (tf32-rounded)
    l0 += __shfl_xor_sync(0xffffffffu, l0, 1);
    l0 += __shfl_xor_sync(0xffffffffu, l0, 2);
    l1 += __shfl_xor_sync(0xffffffffu, l1, 1);
    l1 += __shfl_xor_sync(0xffffffffu, l1, 2);
    float inv0 = 1.f / l0, inv1 = 1.f / l1;

    int b = bh >> 4, h = bh & (NH - 1);
    #pragma unroll
    for (int ni = 0; ni < 8; ni++) {
        int d0 = h * HD + ni * 8 + (lane & 3) * 2;
        float* o0 = g_CTX + (size_t)(b * SEQ + qr0) * EMB + d0;
        float* o1 = g_CTX + (size_t)(b * SEQ + qr0 + 8) * EMB + d0;
        *(float2*)o0 = make_float2(tf32r(oc[ni][0] * inv0), tf32r(oc[ni][1] * inv0));
        *(float2*)o1 = make_float2(tf32r(oc[ni][2] * inv1), tf32r(oc[ni][3] * inv1));
    }
}

// ===========================================================================
// Host
// ===========================================================================
extern "C" void kernel_launch(void* const* d_in, const int* in_sizes, int n_in,
                              void* d_out, int out_size) {
    const float* x  = (const float*)d_in[0];
    const float* Wq = (const float*)d_in[1];
    const float* bq = (const float*)d_in[2];
    const float* Wk = (const float*)d_in[3];
    const float* bk = (const float*)d_in[4];
    const float* Wv = (const float*)d_in[5];
    const float* bv = (const float*)d_in[6];
    const float* Wo = (const float*)d_in[7];
    const float* bo = (const float*)d_in[8];
    float* out = (float*)d_out;

    static bool attr_set = false;
    if (!attr_set) {
        cudaFuncSetAttribute(gemm_tc,
                             cudaFuncAttributeMaxDynamicSharedMemorySize, GEMM_SMEM);
        cudaFuncSetAttribute(attn_tc_kernel,
                             cudaFuncAttributeMaxDynamicSharedMemorySize, ATT_SMEM);
        attr_set = true;
    }

    rope_table_kernel<<<(SEQ * 32) / 256, 256>>>();

    // pre-round x and W's to tf32: (4M + 4M)/4 float4 = 2M threads
    round_kernel<<<(MROWS*EMB/4 + 4*EMB*EMB/4) / 256, 256>>>(x, Wq, Wk, Wv, Wo);

    dim3 ggrid(EMB / 128, MROWS / 128);   // (8, 32)
    gemm_tc<<<ggrid, 256, GEMM_SMEM>>>(bq, nullptr, 2, 0, 0, 0);  // Q (+rope)
    gemm_tc<<<ggrid, 256, GEMM_SMEM>>>(bk, nullptr, 2, 1, 0, 1);  // K (+rope)
    gemm_tc<<<ggrid, 256, GEMM_SMEM>>>(bv, nullptr, 1, 2, 0, 2);  // V

    attn_tc_kernel<<<dim3(SEQ / 64, BATCH * NH), 128, ATT_SMEM>>>();

    gemm_tc<<<ggrid, 256, GEMM_SMEM>>>(bo, out, 0, 3, 1, 3);      // out proj
}

// round 17
// speedup vs baseline: 3.5117x; 1.0002x over previous
#include <cuda_runtime.h>
#include <cstdint>

// Problem constants: B=2, S=2048, E=1024, H=16, D=64
#define NH    16
#define HD    64
#define SEQ   2048
#define BATCH 2
#define EMB   1024
#define MROWS (BATCH*SEQ)   // 4096

// Scratch (device globals — no allocation allowed)
__device__ __align__(16) float g_Q[BATCH*NH*SEQ*HD];
__device__ __align__(16) float g_K[BATCH*NH*SEQ*HD];
__device__ __align__(16) float g_V[BATCH*NH*SEQ*HD];
__device__ __align__(16) float g_CTX[MROWS*EMB];
__device__ __align__(16) float g_Xr[MROWS*EMB];      // tf32-rounded x
__device__ __align__(16) float g_W4[4*EMB*EMB];      // tf32-rounded Wq,Wk,Wv,Wo
__device__ float g_cos[SEQ*32];
__device__ float g_sin[SEQ*32];

// ===========================================================================
// Helpers (all baseline PTX, sm_80+ — NO arch-'a' features)
// ===========================================================================
__device__ __forceinline__ uint32_t smem_u32(const void* p) {
    uint32_t a;
    asm("{ .reg .u64 t; cvta.to.shared.u64 t, %1; cvt.u32.u64 %0, t; }"
        : "=r"(a) : "l"(p));
    return a;
}

__device__ __forceinline__ float tf32r(float x) {
    uint32_t u;
    asm("cvt.rna.tf32.f32 %0, %1;" : "=r"(u) : "f"(x));
    return __uint_as_float(u);
}

__device__ __forceinline__ void cp_async16(void* s, const void* g) {
    uint32_t sa = smem_u32(s);
    asm volatile("cp.async.cg.shared.global [%0], [%1], 16;" :: "r"(sa), "l"(g));
}
#define CP_COMMIT asm volatile("cp.async.commit_group;" ::: "memory")
#define CP_WAIT0  asm volatile("cp.async.wait_group 0;" ::: "memory")
#define CP_WAIT1  asm volatile("cp.async.wait_group 1;" ::: "memory")

// m16n8k8 tf32 MMA, fp32 accumulate
__device__ __forceinline__ void mma8(float* c, const uint32_t* a,
                                     uint32_t b0, uint32_t b1) {
    asm volatile(
        "mma.sync.aligned.m16n8k8.row.col.f32.tf32.tf32.f32 "
        "{%0,%1,%2,%3}, {%4,%5,%6,%7}, {%8,%9}, {%0,%1,%2,%3};"
        : "+f"(c[0]), "+f"(c[1]), "+f"(c[2]), "+f"(c[3])
        : "r"(a[0]), "r"(a[1]), "r"(a[2]), "r"(a[3]), "r"(b0), "r"(b1));
}

// ===========================================================================
// RoPE table
// ===========================================================================
__global__ void rope_table_kernel() {
    int idx = blockIdx.x * blockDim.x + threadIdx.x;
    if (idx >= SEQ * 32) return;
    int pos = idx >> 5;
    int fi  = idx & 31;
    float invf = exp2f(-(float)fi * 0.41524101186092030f);  // log2(10000)/32
    float ang  = (float)pos * invf;
    float s, c;
    sincosf(ang, &s, &c);
    g_cos[idx] = c;
    g_sin[idx] = s;
}

// ===========================================================================
// Pre-round x and all 4 weight matrices to tf32 (round-to-nearest)
// Total: 4M + 4M floats = 2M float4
// ===========================================================================
__global__ void round_kernel(const float* __restrict__ x,
                             const float* __restrict__ Wq,
                             const float* __restrict__ Wk,
                             const float* __restrict__ Wv,
                             const float* __restrict__ Wo) {
    int i = blockIdx.x * 256 + threadIdx.x;
    const int XQ = MROWS * EMB / 4;     // 1M float4
    const int WQ = EMB * EMB / 4;       // 256K float4
    const float4* src;
    float4* dst;
    int off;
    if (i < XQ) {
        src = (const float4*)x; dst = (float4*)g_Xr; off = i;
    } else {
        int j = i - XQ;
        int w = j / WQ, r = j % WQ;
        src = (const float4*)((w == 0) ? Wq : (w == 1) ? Wk : (w == 2) ? Wv : Wo);
        dst = (float4*)(g_W4 + (size_t)w * EMB * EMB);
        off = r;
    }
    float4 v = src[off];
    v.x = tf32r(v.x); v.y = tf32r(v.y); v.z = tf32r(v.z); v.w = tf32r(v.w);
    dst[off] = v;
}

// ===========================================================================
// tf32 mma.sync NT GEMM: C[m,n] = sum_k A[m,k]*W[n,k] + bias[n]
// A, W pre-rounded to tf32. Block tile 128x128xK16, 256 thr (8 warps m64xn32).
//   mode 0: plain -> extout;  mode 1: transpose [b,h,s,d]+tf32-round (V)
//   mode 2: RoPE + transpose + round (Q,K)
//   asel: 0 = g_Xr, 1 = g_CTX;  wsel: 0..3 into g_W4
//   outsel: 0 g_Q, 1 g_K, 2 g_V, 3 extout
// ===========================================================================
#define GPAD 20
#define GSTG 3
#define GEMM_SMEM (GSTG * (128*GPAD + 128*GPAD) * 4)   // 61440 B

__global__ __launch_bounds__(256) void gemm_tc(
    const float* __restrict__ bias, float* __restrict__ extout,
    int mode, int outsel, int asel, int wsel)
{
    extern __shared__ float sm[];
    float* As = sm;                       // [GSTG][128][GPAD]
    float* Bs = sm + GSTG * 128 * GPAD;   // [GSTG][128][GPAD]

    const int tid = threadIdx.x;
    const int wid = tid >> 5, lane = tid & 31;
    const int warp_m = (wid & 1) * 64;    // 2 warps along m
    const int warp_n = (wid >> 1) * 32;   // 4 warps along n
    const int bm = blockIdx.y, bn = blockIdx.x;

    const float* A = (asel == 0) ? g_Xr : g_CTX;
    const float* W = g_W4 + (size_t)wsel * EMB * EMB;
    const float* Ab = A + (size_t)bm * 128 * EMB;
    const float* Wb = W + (size_t)bn * 128 * EMB;

    // stage loader: 128 rows x 16 k per matrix = 512 float4, 2 per thread each
    const int lrow = tid >> 2;           // 0..63? no: v = tid + 256*i
    float c[4][4][4];
    #pragma unroll
    for (int a = 0; a < 4; a++)
        #pragma unroll
        for (int b = 0; b < 4; b++)
            #pragma unroll
            for (int r = 0; r < 4; r++) c[a][b][r] = 0.f;

    auto load_stage = [&](int kt, int stg) {
        float* sa = As + stg * 128 * GPAD;
        float* sb = Bs + stg * 128 * GPAD;
        const float* ga = Ab + kt * 16;
        const float* gb = Wb + kt * 16;
        #pragma unroll
        for (int i = 0; i < 2; i++) {
            int v = tid + 256 * i;
            int row = v >> 2, c4 = (v & 3) * 4;
            cp_async16(&sa[row * GPAD + c4], ga + (size_t)row * EMB + c4);
        }
        #pragma unroll
        for (int i = 0; i < 2; i++) {
            int v = tid + 256 * i;
            int row = v >> 2, c4 = (v & 3) * 4;
            cp_async16(&sb[row * GPAD + c4], gb + (size_t)row * EMB + c4);
        }
    };

    load_stage(0, 0); CP_COMMIT;
    load_stage(1, 1); CP_COMMIT;

    const int NKT = EMB / 16;   // 64
    for (int kt = 0; kt < NKT; kt++) {
        int stg = kt % GSTG;
        if (kt + 2 < NKT) { CP_WAIT1; } else { CP_WAIT0; }
        __syncthreads();
        if (kt + 2 < NKT) { load_stage(kt + 2, (kt + 2) % GSTG); CP_COMMIT; }

        const float* sa = As + stg * 128 * GPAD;
        const float* sb = Bs + stg * 128 * GPAD;
        #pragma unroll
        for (int ks = 0; ks < 2; ks++) {
            uint32_t af[4][4];
            #pragma unroll
            for (int mi = 0; mi < 4; mi++) {
                int r = warp_m + mi * 16 + (lane >> 2);
                int k = ks * 8 + (lane & 3);
                af[mi][0] = __float_as_uint(sa[r * GPAD + k]);
                af[mi][1] = __float_as_uint(sa[(r + 8) * GPAD + k]);
                af[mi][2] = __float_as_uint(sa[r * GPAD + k + 4]);
                af[mi][3] = __float_as_uint(sa[(r + 8) * GPAD + k + 4]);
            }
            uint32_t bf[4][2];
            #pragma unroll
            for (int ni = 0; ni < 4; ni++) {
                int n = warp_n + ni * 8 + (lane >> 2);
                int k = ks * 8 + (lane & 3);
                bf[ni][0] = __float_as_uint(sb[n * GPAD + k]);
                bf[ni][1] = __float_as_uint(sb[n * GPAD + k + 4]);
            }
            #pragma unroll
            for (int mi = 0; mi < 4; mi++)
                #pragma unroll
                for (int ni = 0; ni < 4; ni++)
                    mma8(c[mi][ni], af[mi], bf[ni][0], bf[ni][1]);
        }
    }

    // Epilogue
    float* outp = (outsel == 0) ? g_Q : (outsel == 1) ? g_K :
                  (outsel == 2) ? g_V : extout;

    #pragma unroll
    for (int ni = 0; ni < 4; ni++) {
        int n0 = bn * 128 + warp_n + ni * 8 + (lane & 3) * 2;
        float2 bv = *(const float2*)(bias + n0);
        #pragma unroll
        for (int mi = 0; mi < 4; mi++) {
            int r0 = bm * 128 + warp_m + mi * 16 + (lane >> 2);
            #pragma unroll
            for (int half = 0; half < 2; half++) {
                int mrow = r0 + half * 8;
                float v0 = c[mi][ni][half * 2]     + bv.x;
                float v1 = c[mi][ni][half * 2 + 1] + bv.y;
                if (mode == 0) {
                    *(float2*)(extout + (size_t)mrow * EMB + n0) = make_float2(v0, v1);
                } else {
                    int pos = mrow & (SEQ - 1), b = mrow >> 11;
                    if (mode == 2) {
                        int i0 = n0 & 31;
                        float c0 = g_cos[pos * 32 + i0];
                        float s0 = g_sin[pos * 32 + i0];
                        float c1 = g_cos[pos * 32 + i0 + 1];
                        float s1 = g_sin[pos * 32 + i0 + 1];
                        float r0v = v0 * c0 - v1 * s0;
                        float r1v = v1 * c1 + v0 * s1;
                        v0 = r0v; v1 = r1v;
                    }
                    v0 = tf32r(v0); v1 = tf32r(v1);   // feed attention mma exactly
                    int h = n0 >> 6, d = n0 & (HD - 1);
                    *(float2*)(outp + ((size_t)((b * NH + h) * SEQ + pos)) * HD + d) =
                        make_float2(v0, v1);
                }
            }
        }
    }
}

// ===========================================================================
// tf32 mma.sync flash attention. Block: 128 thr (4 warps), 64 queries,
// KV tiles of 64, double-buffered cp.async. Per warp: 16 q rows.
// S = Q K^T via mma; online softmax on fragments; P -> per-warp smem -> PV mma.
// grid: (SEQ/64, BATCH*NH)
// ===========================================================================
#define APAD 68
#define ATT_SMEM ((2*64*APAD /*K*/ + 2*64*APAD /*V*/ + 4*16*APAD /*P*/) * 4)  // 87040

__global__ __launch_bounds__(128) void attn_tc_kernel() {
    extern __shared__ float sm[];
    float* Ks = sm;                    // [2][64][APAD]
    float* Vs = sm + 2 * 64 * APAD;    // [2][64][APAD]
    float* Ps = sm + 4 * 64 * APAD;    // [4][16][APAD]

    const int tid = threadIdx.x, wid = tid >> 5, lane = tid & 31;
    const int bh = blockIdx.y;
    const int q0 = blockIdx.x * 64;

    const float* Qb = g_Q + (size_t)bh * SEQ * HD;
    const float* Kb = g_K + (size_t)bh * SEQ * HD;
    const float* Vb = g_V + (size_t)bh * SEQ * HD;

    // Q fragments, scaled by 1/8 (exact power of 2, stays tf32-exact)
    uint32_t qa[8][4];
    const int qr0 = q0 + wid * 16 + (lane >> 2);
    #pragma unroll
    for (int kk = 0; kk < 8; kk++) {
        int d0 = kk * 8 + (lane & 3);
        qa[kk][0] = __float_as_uint(0.125f * Qb[(size_t)qr0 * HD + d0]);
        qa[kk][1] = __float_as_uint(0.125f * Qb[(size_t)(qr0 + 8) * HD + d0]);
        qa[kk][2] = __float_as_uint(0.125f * Qb[(size_t)qr0 * HD + d0 + 4]);
        qa[kk][3] = __float_as_uint(0.125f * Qb[(size_t)(qr0 + 8) * HD + d0 + 4]);
    }

    float oc[8][4];
    #pragma unroll
    for (int i = 0; i < 8; i++)
        #pragma unroll
        for (int r = 0; r < 4; r++) oc[i][r] = 0.f;
    float m0 = -1e30f, m1 = -1e30f, l0 = 0.f, l1 = 0.f;

    auto load_kv = [&](int kt, int stg) {
        const float* kg = Kb + (size_t)(kt * 64) * HD;
        const float* vg = Vb + (size_t)(kt * 64) * HD;
        float* ks = Ks + stg * 64 * APAD;
        float* vs = Vs + stg * 64 * APAD;
        #pragma unroll
        for (int i = 0; i < 8; i++) {
            int v = tid + 128 * i;       // 1024 float4 per matrix
            int row = v >> 4, c4 = (v & 15) * 4;
            cp_async16(&ks[row * APAD + c4], kg + row * HD + c4);
            cp_async16(&vs[row * APAD + c4], vg + row * HD + c4);
        }
    };

    load_kv(0, 0); CP_COMMIT;
    const int NT = SEQ / 64;   // 32
    float* pw = Ps + wid * 16 * APAD;

    for (int kt = 0; kt < NT; kt++) {
        int stg = kt & 1;
        CP_WAIT0;
        __syncthreads();
        if (kt + 1 < NT) { load_kv(kt + 1, stg ^ 1); CP_COMMIT; }

        const float* ks = Ks + stg * 64 * APAD;
        const float* vs = Vs + stg * 64 * APAD;

        // ---- S = Q K^T (scaled) ----
        float s[8][4];
        #pragma unroll
        for (int i = 0; i < 8; i++)
            #pragma unroll
            for (int r = 0; r < 4; r++) s[i][r] = 0.f;
        #pragma unroll
        for (int kk = 0; kk < 8; kk++) {
            #pragma unroll
            for (int ni = 0; ni < 8; ni++) {
                int key = ni * 8 + (lane >> 2);
                int d   = kk * 8 + (lane & 3);
                uint32_t b0 = __float_as_uint(ks[key * APAD + d]);
                uint32_t b1 = __float_as_uint(ks[key * APAD + d + 4]);
                mma8(s[ni], qa[kk], b0, b1);
            }
        }

        // ---- online softmax on fragments ----
        float mx0 = -1e30f, mx1 = -1e30f;
        #pragma unroll
        for (int ni = 0; ni < 8; ni++) {
            mx0 = fmaxf(mx0, fmaxf(s[ni][0], s[ni][1]));
            mx1 = fmaxf(mx1, fmaxf(s[ni][2], s[ni][3]));
        }
        mx0 = fmaxf(mx0, __shfl_xor_sync(0xffffffffu, mx0, 1));
        mx0 = fmaxf(mx0, __shfl_xor_sync(0xffffffffu, mx0, 2));
        mx1 = fmaxf(mx1, __shfl_xor_sync(0xffffffffu, mx1, 1));
        mx1 = fmaxf(mx1, __shfl_xor_sync(0xffffffffu, mx1, 2));
        float nm0 = fmaxf(m0, mx0), nm1 = fmaxf(m1, mx1);
        float a0 = __expf(m0 - nm0), a1 = __expf(m1 - nm1);
        l0 *= a0; l1 *= a1;
        #pragma unroll
        for (int ni = 0; ni < 8; ni++) {
            oc[ni][0] *= a0; oc[ni][1] *= a0;
            oc[ni][2] *= a1; oc[ni][3] *= a1;
        }
        m0 = nm0; m1 = nm1;

        #pragma unroll
        for (int ni = 0; ni < 8; ni++) {
            float p00 = __expf(s[ni][0] - m0);
            float p01 = __expf(s[ni][1] - m0);
            float p10 = __expf(s[ni][2] - m1);
            float p11 = __expf(s[ni][3] - m1);
            l0 += p00 + p01;
            l1 += p10 + p11;
            int col = ni * 8 + (lane & 3) * 2;
            *(float2*)&pw[(lane >> 2) * APAD + col] =
                make_float2(tf32r(p00), tf32r(p01));
            *(float2*)&pw[((lane >> 2) + 8) * APAD + col] =
                make_float2(tf32r(p10), tf32r(p11));
        }
        __syncwarp();

        // ---- O += P V ----
        #pragma unroll
        for (int kk = 0; kk < 8; kk++) {
            uint32_t pa[4];
            int kcol = kk * 8 + (lane & 3);
            pa[0] = __float_as_uint(pw[(lane >> 2) * APAD + kcol]);
            pa[1] = __float_as_uint(pw[((lane >> 2) + 8) * APAD + kcol]);
            pa[2] = __float_as_uint(pw[(lane >> 2) * APAD + kcol + 4]);
            pa[3] = __float_as_uint(pw[((lane >> 2) + 8) * APAD + kcol + 4]);
            #pragma unroll
            for (int ni = 0; ni < 8; ni++) {
                int key = kk * 8 + (lane & 3);
                int d   = ni * 8 + (lane >> 2);
                uint32_t b0 = __float_as_uint(vs[key * APAD + d]);
                uint32_t b1 = __float_as_uint(vs[(key + 4) * APAD + d]);
                mma8(oc[ni], pa, b0, b1);
            }
        }
        __syncwarp();
    }

    // finalize: row sums across quad, normalize, store to g_CTX (tf32-rounded)
    l0 += __shfl_xor_sync(0xffffffffu, l0, 1);
    l0 += __shfl_xor_sync(0xffffffffu, l0, 2);
    l1 += __shfl_xor_sync(0xffffffffu, l1, 1);
    l1 += __shfl_xor_sync(0xffffffffu, l1, 2);
    float inv0 = 1.f / l0, inv1 = 1.f / l1;

    int b = bh >> 4, h = bh & (NH - 1);
    #pragma unroll
    for (int ni = 0; ni < 8; ni++) {
        int d0 = h * HD + ni * 8 + (lane & 3) * 2;
        float* o0 = g_CTX + (size_t)(b * SEQ + qr0) * EMB + d0;
        float* o1 = g_CTX + (size_t)(b * SEQ + qr0 + 8) * EMB + d0;
        *(float2*)o0 = make_float2(tf32r(oc[ni][0] * inv0), tf32r(oc[ni][1] * inv0));
        *(float2*)o1 = make_float2(tf32r(oc[ni][2] * inv1), tf32r(oc[ni][3] * inv1));
    }
}

// ===========================================================================
// Host
// ===========================================================================
extern "C" void kernel_launch(void* const* d_in, const int* in_sizes, int n_in,
                              void* d_out, int out_size) {
    const float* x  = (const float*)d_in[0];
    const float* Wq = (const float*)d_in[1];
    const float* bq = (const float*)d_in[2];
    const float* Wk = (const float*)d_in[3];
    const float* bk = (const float*)d_in[4];
    const float* Wv = (const float*)d_in[5];
    const float* bv = (const float*)d_in[6];
    const float* Wo = (const float*)d_in[7];
    const float* bo = (const float*)d_in[8];
    float* out = (float*)d_out;

    static bool attr_set = false;
    if (!attr_set) {
        cudaFuncSetAttribute(gemm_tc,
                             cudaFuncAttributeMaxDynamicSharedMemorySize, GEMM_SMEM);
        cudaFuncSetAttribute(attn_tc_kernel,
                             cudaFuncAttributeMaxDynamicSharedMemorySize, ATT_SMEM);
        attr_set = true;
    }

    rope_table_kernel<<<(SEQ * 32) / 256, 256>>>();

    // pre-round x and W's to tf32: (4M + 4M)/4 float4 = 2M threads
    round_kernel<<<(MROWS*EMB/4 + 4*EMB*EMB/4) / 256, 256>>>(x, Wq, Wk, Wv, Wo);

    dim3 ggrid(EMB / 128, MROWS / 128);   // (8, 32)
    gemm_tc<<<ggrid, 256, GEMM_SMEM>>>(bq, nullptr, 2, 0, 0, 0);  // Q (+rope)
    gemm_tc<<<ggrid, 256, GEMM_SMEM>>>(bk, nullptr, 2, 1, 0, 1);  // K (+rope)
    gemm_tc<<<ggrid, 256, GEMM_SMEM>>>(bv, nullptr, 1, 2, 0, 2);  // V

    attn_tc_kernel<<<dim3(SEQ / 64, BATCH * NH), 128, ATT_SMEM>>>();

    gemm_tc<<<ggrid, 256, GEMM_SMEM>>>(bo, out, 0, 3, 1, 3);      // out proj
}